// round 1
// baseline (speedup 1.0000x reference)
#include <cuda_runtime.h>
#include <math.h>

// Scratch: per-segment power-basis coefficients, folded with the Bezier matrix.
// Layout: g_coeffs[2*s+0] = {c0.x, c0.y, c1.x, c1.y}
//         g_coeffs[2*s+1] = {c2.x, c2.y, c3.x, c3.y}
// Max S = 4096 -> 8192 float4 = 128 KB.
#define MAX_S 4096
__device__ float4 g_coeffs[2 * MAX_S];

__global__ void spline_coeff_kernel(const float2* __restrict__ ctrl,
                                    const float2* __restrict__ joint,
                                    int S) {
    int s = blockIdx.x * blockDim.x + threadIdx.x;
    if (s >= S) return;
    float2 p0 = joint[s];
    float2 p3 = joint[s + 1];
    float2 p1 = ctrl[2 * s];
    float2 p2 = ctrl[2 * s + 1];

    // Bezier characteristic matrix rows applied to points:
    // c0 =  p0
    // c1 = -3 p0 + 3 p1
    // c2 =  3 p0 - 6 p1 + 3 p2
    // c3 = -  p0 + 3 p1 - 3 p2 + p3
    float c0x = p0.x;
    float c0y = p0.y;
    float c1x = 3.0f * (p1.x - p0.x);
    float c1y = 3.0f * (p1.y - p0.y);
    float c2x = 3.0f * p0.x - 6.0f * p1.x + 3.0f * p2.x;
    float c2y = 3.0f * p0.y - 6.0f * p1.y + 3.0f * p2.y;
    float c3x = -p0.x + 3.0f * p1.x - 3.0f * p2.x + p3.x;
    float c3y = -p0.y + 3.0f * p1.y - 3.0f * p2.y + p3.y;

    g_coeffs[2 * s + 0] = make_float4(c0x, c0y, c1x, c1y);
    g_coeffs[2 * s + 1] = make_float4(c2x, c2y, c3x, c3y);
}

__global__ void __launch_bounds__(256)
spline_eval_kernel(const float4* __restrict__ t4,
                   float4* __restrict__ out4,
                   int n4,            // number of float4 groups (n/4, exact for this problem)
                   int n,             // total samples
                   float Sf,          // (float)S
                   int S) {
    int i = blockIdx.x * blockDim.x + threadIdx.x;
    if (i >= n4) return;

    float4 tv = t4[i];
    float ts[4] = {tv.x, tv.y, tv.z, tv.w};
    float rx[4], ry[4];

#pragma unroll
    for (int j = 0; j < 4; j++) {
        float tc = fminf(ts[j], 1.0f);       // reference clamp (1-1e-10 rounds to 1.0f)
        float u = Sf * tc;
        int seg = (int)floorf(u);
        float lt = u - (float)seg;
        if (seg >= S) { seg = S - 1; lt = 1.0f; }

        float4 a = g_coeffs[2 * seg + 0];    // c0.x c0.y c1.x c1.y
        float4 b = g_coeffs[2 * seg + 1];    // c2.x c2.y c3.x c3.y

        float lt2 = lt * lt;
        float lt3 = lt2 * lt;
        // c0 + c1*t + c2*t^2 + c3*t^3 (power-basis sum, same order as reference)
        rx[j] = fmaf(b.z, lt3, fmaf(b.x, lt2, fmaf(a.z, lt, a.x)));
        ry[j] = fmaf(b.w, lt3, fmaf(b.y, lt2, fmaf(a.w, lt, a.y)));
    }

    out4[2 * i + 0] = make_float4(rx[0], ry[0], rx[1], ry[1]);
    out4[2 * i + 1] = make_float4(rx[2], ry[2], rx[3], ry[3]);
}

// Scalar tail kernel for n % 4 != 0 (not hit for N=8388608, kept for safety)
__global__ void spline_eval_tail(const float* __restrict__ t,
                                 float2* __restrict__ out,
                                 int start, int n, float Sf, int S) {
    int i = start + blockIdx.x * blockDim.x + threadIdx.x;
    if (i >= n) return;
    float tc = fminf(t[i], 1.0f);
    float u = Sf * tc;
    int seg = (int)floorf(u);
    float lt = u - (float)seg;
    if (seg >= S) { seg = S - 1; lt = 1.0f; }
    float4 a = g_coeffs[2 * seg + 0];
    float4 b = g_coeffs[2 * seg + 1];
    float lt2 = lt * lt;
    float lt3 = lt2 * lt;
    float x = fmaf(b.z, lt3, fmaf(b.x, lt2, fmaf(a.z, lt, a.x)));
    float y = fmaf(b.w, lt3, fmaf(b.y, lt2, fmaf(a.w, lt, a.y)));
    out[i] = make_float2(x, y);
}

extern "C" void kernel_launch(void* const* d_in, const int* in_sizes, int n_in,
                              void* d_out, int out_size) {
    const float* t = (const float*)d_in[0];
    const float2* ctrl = (const float2*)d_in[1];    // (S*2, 2) floats
    const float2* joint = (const float2*)d_in[2];   // (S+1, 2) floats

    int n = in_sizes[0];
    int S = in_sizes[2] / 2 - 1;                    // joint_points has (S+1)*2 floats

    // 1) fold Bezier matrix into per-segment coeffs (tiny)
    {
        int threads = 256;
        int blocks = (S + threads - 1) / threads;
        spline_coeff_kernel<<<blocks, threads>>>(ctrl, joint, S);
    }

    // 2) streaming evaluation
    int n4 = n / 4;
    if (n4 > 0) {
        int threads = 256;
        int blocks = (n4 + threads - 1) / threads;
        spline_eval_kernel<<<blocks, threads>>>((const float4*)t, (float4*)d_out,
                                                n4, n, (float)S, S);
    }
    int rem = n - n4 * 4;
    if (rem > 0) {
        spline_eval_tail<<<1, 128>>>(t, (float2*)d_out, n4 * 4, n, (float)S, S);
    }
}

// round 2
// speedup vs baseline: 1.0038x; 1.0038x over previous
#include <cuda_runtime.h>
#include <math.h>

// Per-segment power-basis coefficients (Bezier matrix folded in).
// g_coeffs[2*s+0] = {c0.x, c0.y, c1.x, c1.y}
// g_coeffs[2*s+1] = {c2.x, c2.y, c3.x, c3.y}
#define MAX_S 4096
__device__ float4 g_coeffs[2 * MAX_S];

// Segments stageable in shared memory per block. t is sorted, so a block of
// 1024 consecutive samples spans ~0.5 segments on average; 128 is enormous
// headroom (128 * 32B = 4 KB smem).
#define SMEM_SEGS 128

__global__ void spline_coeff_kernel(const float2* __restrict__ ctrl,
                                    const float2* __restrict__ joint,
                                    int S) {
    int s = blockIdx.x * blockDim.x + threadIdx.x;
    if (s >= S) return;
    float2 p0 = joint[s];
    float2 p3 = joint[s + 1];
    float2 p1 = ctrl[2 * s];
    float2 p2 = ctrl[2 * s + 1];

    float c0x = p0.x;
    float c0y = p0.y;
    float c1x = 3.0f * (p1.x - p0.x);
    float c1y = 3.0f * (p1.y - p0.y);
    float c2x = 3.0f * p0.x - 6.0f * p1.x + 3.0f * p2.x;
    float c2y = 3.0f * p0.y - 6.0f * p1.y + 3.0f * p2.y;
    float c3x = -p0.x + 3.0f * p1.x - 3.0f * p2.x + p3.x;
    float c3y = -p0.y + 3.0f * p1.y - 3.0f * p2.y + p3.y;

    g_coeffs[2 * s + 0] = make_float4(c0x, c0y, c1x, c1y);
    g_coeffs[2 * s + 1] = make_float4(c2x, c2y, c3x, c3y);
}

__global__ void __launch_bounds__(256)
spline_eval_kernel(const float4* __restrict__ t4,
                   float4* __restrict__ out4,
                   int n4, float Sf, int S) {
    __shared__ float4 s_coeff[2 * SMEM_SEGS];
    __shared__ int s_lo, s_hi;

    int i = blockIdx.x * blockDim.x + threadIdx.x;
    bool valid = (i < n4);

    float4 tv = valid ? t4[i] : make_float4(0.f, 0.f, 0.f, 0.f);
    float ts[4] = {tv.x, tv.y, tv.z, tv.w};

    int   seg[4];
    float lt[4];
#pragma unroll
    for (int j = 0; j < 4; j++) {
        float tc = fminf(ts[j], 1.0f);
        float u = Sf * tc;
        int sg = (int)floorf(u);
        float l = u - (float)sg;
        if (sg >= S) { sg = S - 1; l = 1.0f; }
        seg[j] = sg;
        lt[j] = l;
    }

    // Block-wide segment range (t sorted -> per-thread min is seg[0], max is seg[3])
    if (threadIdx.x == 0) { s_lo = 0x7FFFFFFF; s_hi = -1; }
    __syncthreads();
    if (valid) {
        atomicMin(&s_lo, seg[0]);
        atomicMax(&s_hi, seg[3]);
    }
    __syncthreads();

    int lo = s_lo;
    int cnt = s_hi - lo + 1;
    bool use_smem = (s_hi >= lo) && (cnt <= SMEM_SEGS);

    if (use_smem) {
        for (int k = threadIdx.x; k < 2 * cnt; k += blockDim.x)
            s_coeff[k] = g_coeffs[2 * lo + k];
        __syncthreads();
    }

    if (!valid) return;

    float rx[4], ry[4];
#pragma unroll
    for (int j = 0; j < 4; j++) {
        float4 a, b;
        if (use_smem) {
            int rel = seg[j] - lo;
            a = s_coeff[2 * rel + 0];
            b = s_coeff[2 * rel + 1];
        } else {
            a = g_coeffs[2 * seg[j] + 0];
            b = g_coeffs[2 * seg[j] + 1];
        }
        float l = lt[j];
        float l2 = l * l;
        float l3 = l2 * l;
        rx[j] = fmaf(b.z, l3, fmaf(b.x, l2, fmaf(a.z, l, a.x)));
        ry[j] = fmaf(b.w, l3, fmaf(b.y, l2, fmaf(a.w, l, a.y)));
    }

    out4[2 * i + 0] = make_float4(rx[0], ry[0], rx[1], ry[1]);
    out4[2 * i + 1] = make_float4(rx[2], ry[2], rx[3], ry[3]);
}

// Scalar tail for n % 4 != 0 (not hit for N = 8388608)
__global__ void spline_eval_tail(const float* __restrict__ t,
                                 float2* __restrict__ out,
                                 int start, int n, float Sf, int S) {
    int i = start + blockIdx.x * blockDim.x + threadIdx.x;
    if (i >= n) return;
    float tc = fminf(t[i], 1.0f);
    float u = Sf * tc;
    int sg = (int)floorf(u);
    float l = u - (float)sg;
    if (sg >= S) { sg = S - 1; l = 1.0f; }
    float4 a = g_coeffs[2 * sg + 0];
    float4 b = g_coeffs[2 * sg + 1];
    float l2 = l * l;
    float l3 = l2 * l;
    float x = fmaf(b.z, l3, fmaf(b.x, l2, fmaf(a.z, l, a.x)));
    float y = fmaf(b.w, l3, fmaf(b.y, l2, fmaf(a.w, l, a.y)));
    out[i] = make_float2(x, y);
}

extern "C" void kernel_launch(void* const* d_in, const int* in_sizes, int n_in,
                              void* d_out, int out_size) {
    const float* t = (const float*)d_in[0];
    const float2* ctrl = (const float2*)d_in[1];
    const float2* joint = (const float2*)d_in[2];

    int n = in_sizes[0];
    int S = in_sizes[2] / 2 - 1;

    {
        int threads = 256;
        int blocks = (S + threads - 1) / threads;
        spline_coeff_kernel<<<blocks, threads>>>(ctrl, joint, S);
    }

    int n4 = n / 4;
    if (n4 > 0) {
        int threads = 256;
        int blocks = (n4 + threads - 1) / threads;
        spline_eval_kernel<<<blocks, threads>>>((const float4*)t, (float4*)d_out,
                                                n4, (float)S, S);
    }
    int rem = n - n4 * 4;
    if (rem > 0) {
        spline_eval_tail<<<1, 128>>>(t, (float2*)d_out, n4 * 4, n, (float)S, S);
    }
}